// round 6
// baseline (speedup 1.0000x reference)
#include <cuda_runtime.h>
#include <cuda_fp16.h>
#include <cstdint>

#define D_VOCAB 262
#define D_EMB   128
#define NTAP    5
#define CW      16
#define NSEQ    32768
#define NCHUNK  74
#define THREADS 640
// main smem: [NTAP*D_VOCAB] rows of 64 channels (8 x uint4) = 167,680 bytes
#define SMEM_BYTES (NTAP * D_VOCAB * 32 * 4)
// uint4-unit stride of one tap plane: 262 rows * 8 uint4
#define TAPSTRIDE16 (D_VOCAB * 8)

// precompute smem: ws[i][k*32+eL] padded row stride 164 floats
#define WROW 164
#define PRE_SMEM (D_EMB * WROW * 4)   // 83,968 B
#define PRE_THREADS 160

// fp16 contrib table: [tap][vocab][emb]
__device__ __align__(16) __half g_tab[NTAP * D_VOCAB * D_EMB];

// ---------------------------------------------------------------------------
// Fused transpose+precompute:
//   contrib[k][v][e] = sum_i conv_w[e,i,k] * emb[v,i]  (fp32 -> fp16)
// Grid (66, 4): x = 4-vocab group, y = 32-e group. 160 threads.
// ---------------------------------------------------------------------------
__global__ void __launch_bounds__(PRE_THREADS, 1)
precompute_fused(const float* __restrict__ conv_w,
                 const float* __restrict__ emb) {
    extern __shared__ float ws[];
    const int tid = threadIdx.x;
    const int v0 = blockIdx.x * 4;
    const int e0 = blockIdx.y * 32;

    // Stage: 32 e-rows x 640 floats, coalesced; transpose into padded smem.
    const float4* __restrict__ cw4 = (const float4*)conv_w;
    #pragma unroll 4
    for (int r = 0; r < 32; ++r) {
        float4 w = __ldg(&cw4[(size_t)(e0 + r) * 160 + tid]);
        const int j = 4 * tid;
        ws[((j + 0) / 5) * WROW + ((j + 0) % 5) * 32 + r] = w.x;
        ws[((j + 1) / 5) * WROW + ((j + 1) % 5) * 32 + r] = w.y;
        ws[((j + 2) / 5) * WROW + ((j + 2) % 5) * 32 + r] = w.z;
        ws[((j + 3) / 5) * WROW + ((j + 3) % 5) * 32 + r] = w.w;
    }
    __syncthreads();

    const int k = tid >> 5;          // 0..4
    const int eL = tid & 31;
    const float* __restrict__ wcol = ws + k * 32 + eL;
    const float4* __restrict__ emb4 = (const float4*)emb;

    float acc[4];
    #pragma unroll
    for (int v = 0; v < 4; ++v) acc[v] = 0.f;

    #pragma unroll 4
    for (int i4 = 0; i4 < 32; ++i4) {
        const float w0 = wcol[(i4 * 4 + 0) * WROW];
        const float w1 = wcol[(i4 * 4 + 1) * WROW];
        const float w2 = wcol[(i4 * 4 + 2) * WROW];
        const float w3 = wcol[(i4 * 4 + 3) * WROW];
        #pragma unroll
        for (int v = 0; v < 4; ++v) {
            const int vv = v0 + v;
            if (vv < D_VOCAB) {
                float4 em = __ldg(&emb4[vv * 32 + i4]);
                acc[v] = fmaf(em.x, w0, acc[v]);
                acc[v] = fmaf(em.y, w1, acc[v]);
                acc[v] = fmaf(em.z, w2, acc[v]);
                acc[v] = fmaf(em.w, w3, acc[v]);
            }
        }
    }

    #pragma unroll
    for (int v = 0; v < 4; ++v) {
        const int vv = v0 + v;
        if (vv < D_VOCAB)
            g_tab[(k * D_VOCAB + vv) * D_EMB + e0 + eL] = __float2half(acc[v]);
    }
}

// ---------------------------------------------------------------------------
// half2 x4 helpers on uint4-packed fp16
// ---------------------------------------------------------------------------
__device__ __forceinline__ uint4 h2add4(uint4 a, uint4 b) {
    uint4 r;
    *(__half2*)&r.x = __hadd2(*(const __half2*)&a.x, *(const __half2*)&b.x);
    *(__half2*)&r.y = __hadd2(*(const __half2*)&a.y, *(const __half2*)&b.y);
    *(__half2*)&r.z = __hadd2(*(const __half2*)&a.z, *(const __half2*)&b.z);
    *(__half2*)&r.w = __hadd2(*(const __half2*)&a.w, *(const __half2*)&b.w);
    return r;
}
__device__ __forceinline__ uint4 h2max4(uint4 a, uint4 b) {
    uint4 r;
    *(__half2*)&r.x = __hmax2(*(const __half2*)&a.x, *(const __half2*)&b.x);
    *(__half2*)&r.y = __hmax2(*(const __half2*)&a.y, *(const __half2*)&b.y);
    *(__half2*)&r.z = __hmax2(*(const __half2*)&a.z, *(const __half2*)&b.z);
    *(__half2*)&r.w = __hmax2(*(const __half2*)&a.w, *(const __half2*)&b.w);
    return r;
}

// ---------------------------------------------------------------------------
// Main kernel. Grid (74, 2): x = sequence chunk (443 seqs), y = 64-ch group.
// CTA stages its 5x262x64 fp16 table slice (164 KB smem), 1 CTA/SM, 1 wave.
// 640 threads = 20 warps/SM. Quarter-warp split: 4 seqs per warp-iter;
// lane owns 8 channels (16 B) -> LDS.128 gathers, conflict-free, 4 chains.
// Id loads software-pipelined in raw form (converted only at use).
// ---------------------------------------------------------------------------
__global__ void __launch_bounds__(THREADS, 1)
conv_char_kernel(const int* __restrict__ ids_raw,
                 const float* __restrict__ conv_b,
                 float* __restrict__ out) {
    extern __shared__ uint4 s_tab16[];
    const int g = blockIdx.y;
    const int lane = threadIdx.x & 31;
    const int warp = threadIdx.x >> 5;
    const int l7 = lane & 7;
    const int q = lane >> 3;             // 0..3: which sequence of the group

    // Per-warp int64-vs-int32 detection (no shared, no sync needed).
    int s2;
    {
        int v = ids_raw[2 * lane + 1] | ids_raw[64 + 2 * lane + 1];
        s2 = (__ballot_sync(0xffffffffu, v != 0) == 0u) ? 1 : 0;
    }

    const int chunk = (NSEQ + NCHUNK - 1) / NCHUNK;  // 443
    const int base = blockIdx.x * chunk;
    const int end = min(base + chunk, NSEQ);
    const int step = 4 * (THREADS / 32);             // 80

    // Prefetch first iteration's raw id words BEFORE staging (overlaps).
    uint4 raw[8];
    {
        const int nc = min(base + 4 * warp + q, end - 1);
        if (s2) {
            const uint4* p = (const uint4*)(ids_raw + (size_t)nc * 32);
            #pragma unroll
            for (int j = 0; j < 8; ++j) raw[j] = __ldg(&p[j]);
        } else {
            const uint4* p = (const uint4*)(ids_raw + (size_t)nc * 16);
            #pragma unroll
            for (int j = 0; j < 4; ++j) raw[j] = __ldg(&p[j]);
        }
    }

    // Stage table slice: coalesced uint4 copies (10480 x 16 B).
    {
        const char* gb = (const char*)g_tab;
        for (int idx = threadIdx.x; idx < NTAP * D_VOCAB * 8; idx += THREADS) {
            int r = idx >> 3, c = idx & 7;
            s_tab16[idx] = *(const uint4*)(gb + (size_t)r * 256 + g * 128 + c * 16);
        }
    }
    __syncthreads();

    for (int n0 = base + 4 * warp; n0 < end; n0 += step) {
        const int nsel = n0 + q;

        // Convert raw -> gather indices a[c] = id*8 + l7.
        int a[CW];
        if (s2) {
            #pragma unroll
            for (int j = 0; j < 8; ++j) {
                a[2 * j]     = (int)raw[j].x * 8 + l7;
                a[2 * j + 1] = (int)raw[j].z * 8 + l7;
            }
        } else {
            #pragma unroll
            for (int j = 0; j < 4; ++j) {
                a[4 * j]     = (int)raw[j].x * 8 + l7;
                a[4 * j + 1] = (int)raw[j].y * 8 + l7;
                a[4 * j + 2] = (int)raw[j].z * 8 + l7;
                a[4 * j + 3] = (int)raw[j].w * 8 + l7;
            }
        }

        // Issue next iteration's id loads now; latency hides under t-loop.
        {
            const int nn = n0 + step + q;
            const int nc = min(nn < end ? nn : (end - 1), end - 1);
            if (s2) {
                const uint4* p = (const uint4*)(ids_raw + (size_t)nc * 32);
                #pragma unroll
                for (int j = 0; j < 8; ++j) raw[j] = __ldg(&p[j]);
            } else {
                const uint4* p = (const uint4*)(ids_raw + (size_t)nc * 16);
                #pragma unroll
                for (int j = 0; j < 4; ++j) raw[j] = __ldg(&p[j]);
            }
        }

        // Even/odd-t max chains on 8 channels (4 half2) per lane.
        uint4 me, mo;
        #pragma unroll
        for (int t = 0; t < CW; ++t) {
            const int klo = (t < 2) ? (2 - t) : 0;
            const int khi = (t > CW - 3) ? (CW + 1 - t) : NTAP - 1;  // inclusive

            uint4 s[NTAP];
            #pragma unroll
            for (int k = 0; k < NTAP; ++k) {
                if (k < klo || k > khi) continue;
                s[k] = s_tab16[k * TAPSTRIDE16 + a[t + k - 2]];
            }

            uint4 y;
            const int nv = khi - klo + 1;
            if (nv == 5) {
                y = h2add4(h2add4(h2add4(s[0], s[1]), h2add4(s[2], s[3])), s[4]);
            } else if (nv == 4) {
                y = h2add4(h2add4(s[klo], s[klo + 1]), h2add4(s[klo + 2], s[klo + 3]));
            } else {  // nv == 3
                y = h2add4(h2add4(s[klo], s[klo + 1]), s[klo + 2]);
            }

            if (t == 0)      me = y;
            else if (t == 1) mo = y;
            else if ((t & 1) == 0) me = h2max4(me, y);
            else                   mo = h2max4(mo, y);
        }
        const uint4 m = h2max4(me, mo);

        if (nsel < end) {
            // Bias loaded here (L1-resident), not held in registers.
            const float4 bias0 = __ldg((const float4*)(conv_b + g * 64 + l7 * 8));
            const float4 bias1 = __ldg((const float4*)(conv_b + g * 64 + l7 * 8 + 4));
            float2 c0 = __half22float2(*(const __half2*)&m.x);
            float2 c1 = __half22float2(*(const __half2*)&m.y);
            float2 c2 = __half22float2(*(const __half2*)&m.z);
            float2 c3 = __half22float2(*(const __half2*)&m.w);
            float4 o0, o1;
            o0.x = c0.x + bias0.x; o0.y = c0.y + bias0.y;
            o0.z = c1.x + bias0.z; o0.w = c1.y + bias0.w;
            o1.x = c2.x + bias1.x; o1.y = c2.y + bias1.y;
            o1.z = c3.x + bias1.z; o1.w = c3.y + bias1.w;
            float* op = out + (size_t)nsel * D_EMB + g * 64 + l7 * 8;
            *(float4*)op = o0;
            *(float4*)(op + 4) = o1;
        }
    }
}

// ---------------------------------------------------------------------------
extern "C" void kernel_launch(void* const* d_in, const int* in_sizes, int n_in,
                              void* d_out, int out_size) {
    const int* input = nullptr;
    const float* emb = nullptr;
    const float* conv_w = nullptr;
    const float* conv_b = nullptr;
    for (int i = 0; i < n_in; ++i) {
        switch (in_sizes[i]) {
            case 524288: input  = (const int*)d_in[i];   break;  // ids [128,256,16]
            case 33536:  emb    = (const float*)d_in[i]; break;  // [262,128]
            case 81920:  conv_w = (const float*)d_in[i]; break;  // [128,128,5]
            case 128:    conv_b = (const float*)d_in[i]; break;  // [128]
            default: break;  // lengths (32768) unused
        }
    }

    cudaFuncSetAttribute(precompute_fused,
                         cudaFuncAttributeMaxDynamicSharedMemorySize, PRE_SMEM);
    precompute_fused<<<dim3(66, 4), PRE_THREADS, PRE_SMEM>>>(conv_w, emb);

    cudaFuncSetAttribute(conv_char_kernel,
                         cudaFuncAttributeMaxDynamicSharedMemorySize, SMEM_BYTES);
    conv_char_kernel<<<dim3(NCHUNK, 2), THREADS, SMEM_BYTES>>>(
        input, conv_b, (float*)d_out);
}

// round 7
// speedup vs baseline: 1.0638x; 1.0638x over previous
#include <cuda_runtime.h>
#include <cuda_fp16.h>
#include <cstdint>

#define D_VOCAB 262
#define D_EMB   128
#define NTAP    5
#define CW      16
#define NSEQ    32768
#define NCHUNK  74
#define THREADS 768
#define CHUNK   443                     // ceil(32768/74)
// table region: [NTAP*D_VOCAB] rows of 64 channels (8 x uint4) = 167,680 B
#define TAB_BYTES (NTAP * D_VOCAB * 32 * 4)
// ids region: CHUNK*16 int32 = 28,352 B ; total 196,032 B
#define SMEM_BYTES (TAB_BYTES + CHUNK * CW * 4)
// uint4-unit stride of one tap plane: 262 rows * 8 uint4
#define TAPSTRIDE16 (D_VOCAB * 8)

// precompute smem: ws[i][k*32+eL] padded row stride 164 floats
#define WROW 164
#define PRE_SMEM (D_EMB * WROW * 4)   // 83,968 B
#define PRE_THREADS 160

// fp16 contrib table: [tap][vocab][emb]
__device__ __align__(16) __half g_tab[NTAP * D_VOCAB * D_EMB];

// ---------------------------------------------------------------------------
// Fused transpose+precompute:
//   contrib[k][v][e] = sum_i conv_w[e,i,k] * emb[v,i]  (fp32 -> fp16)
// Grid (66, 4): x = 4-vocab group, y = 32-e group. 160 threads.
// ---------------------------------------------------------------------------
__global__ void __launch_bounds__(PRE_THREADS, 1)
precompute_fused(const float* __restrict__ conv_w,
                 const float* __restrict__ emb) {
    extern __shared__ float ws[];
    const int tid = threadIdx.x;
    const int v0 = blockIdx.x * 4;
    const int e0 = blockIdx.y * 32;

    const float4* __restrict__ cw4 = (const float4*)conv_w;
    #pragma unroll 4
    for (int r = 0; r < 32; ++r) {
        float4 w = __ldg(&cw4[(size_t)(e0 + r) * 160 + tid]);
        const int j = 4 * tid;
        ws[((j + 0) / 5) * WROW + ((j + 0) % 5) * 32 + r] = w.x;
        ws[((j + 1) / 5) * WROW + ((j + 1) % 5) * 32 + r] = w.y;
        ws[((j + 2) / 5) * WROW + ((j + 2) % 5) * 32 + r] = w.z;
        ws[((j + 3) / 5) * WROW + ((j + 3) % 5) * 32 + r] = w.w;
    }
    __syncthreads();

    const int k = tid >> 5;          // 0..4
    const int eL = tid & 31;
    const float* __restrict__ wcol = ws + k * 32 + eL;
    const float4* __restrict__ emb4 = (const float4*)emb;

    float acc[4];
    #pragma unroll
    for (int v = 0; v < 4; ++v) acc[v] = 0.f;

    #pragma unroll 4
    for (int i4 = 0; i4 < 32; ++i4) {
        const float w0 = wcol[(i4 * 4 + 0) * WROW];
        const float w1 = wcol[(i4 * 4 + 1) * WROW];
        const float w2 = wcol[(i4 * 4 + 2) * WROW];
        const float w3 = wcol[(i4 * 4 + 3) * WROW];
        #pragma unroll
        for (int v = 0; v < 4; ++v) {
            const int vv = v0 + v;
            if (vv < D_VOCAB) {
                float4 em = __ldg(&emb4[vv * 32 + i4]);
                acc[v] = fmaf(em.x, w0, acc[v]);
                acc[v] = fmaf(em.y, w1, acc[v]);
                acc[v] = fmaf(em.z, w2, acc[v]);
                acc[v] = fmaf(em.w, w3, acc[v]);
            }
        }
    }

    #pragma unroll
    for (int v = 0; v < 4; ++v) {
        const int vv = v0 + v;
        if (vv < D_VOCAB)
            g_tab[(k * D_VOCAB + vv) * D_EMB + e0 + eL] = __float2half(acc[v]);
    }
}

// ---------------------------------------------------------------------------
// half2 x4 helpers on uint4-packed fp16
// ---------------------------------------------------------------------------
__device__ __forceinline__ uint4 h2add4(uint4 a, uint4 b) {
    uint4 r;
    *(__half2*)&r.x = __hadd2(*(const __half2*)&a.x, *(const __half2*)&b.x);
    *(__half2*)&r.y = __hadd2(*(const __half2*)&a.y, *(const __half2*)&b.y);
    *(__half2*)&r.z = __hadd2(*(const __half2*)&a.z, *(const __half2*)&b.z);
    *(__half2*)&r.w = __hadd2(*(const __half2*)&a.w, *(const __half2*)&b.w);
    return r;
}
__device__ __forceinline__ uint4 h2max4(uint4 a, uint4 b) {
    uint4 r;
    *(__half2*)&r.x = __hmax2(*(const __half2*)&a.x, *(const __half2*)&b.x);
    *(__half2*)&r.y = __hmax2(*(const __half2*)&a.y, *(const __half2*)&b.y);
    *(__half2*)&r.z = __hmax2(*(const __half2*)&a.z, *(const __half2*)&b.z);
    *(__half2*)&r.w = __hmax2(*(const __half2*)&a.w, *(const __half2*)&b.w);
    return r;
}

// ---------------------------------------------------------------------------
// Main kernel. Grid (74, 2): x = sequence chunk (<=443 seqs), y = 64-ch group.
// CTA stages table slice (164 KB) AND its whole id chunk (28 KB) in smem.
// 768 threads = 24 warps/SM. Quarter-warp split: 4 seqs per warp-iter;
// lane owns 8 channels (16 B) -> LDS.128 gathers, conflict-free, 4 chains.
// No mid-loop LDG: ids come from smem (broadcast LDS.128), minimal regs.
// ---------------------------------------------------------------------------
__global__ void __launch_bounds__(THREADS, 1)
conv_char_kernel(const int* __restrict__ ids_raw,
                 const float* __restrict__ conv_b,
                 float* __restrict__ out) {
    extern __shared__ uint4 s_tab16[];
    int* s_ids = (int*)(s_tab16 + NTAP * D_VOCAB * 8);   // [CHUNK*16]
    const int g = blockIdx.y;
    const int lane = threadIdx.x & 31;
    const int warp = threadIdx.x >> 5;
    const int l7 = lane & 7;
    const int q = lane >> 3;             // 0..3: which sequence of the group

    // Per-warp int64-vs-int32 detection (int64 ids < 262 -> zero high words).
    int s2;
    {
        int v = ids_raw[2 * lane + 1] | ids_raw[64 + 2 * lane + 1];
        s2 = (__ballot_sync(0xffffffffu, v != 0) == 0u) ? 1 : 0;
    }

    const int base = blockIdx.x * CHUNK;
    const int end = min(base + CHUNK, NSEQ);
    const int nid = (end - base) * CW;

    // Stage ids for this chunk: int64 -> int32 narrowing (or direct copy).
    if (s2) {
        const int* src = ids_raw + (size_t)base * 32;    // int64 as int pairs
        for (int i = threadIdx.x; i < nid; i += THREADS)
            s_ids[i] = src[2 * i];
    } else {
        const int* src = ids_raw + (size_t)base * CW;
        for (int i = threadIdx.x; i < nid; i += THREADS)
            s_ids[i] = src[i];
    }

    // Stage table slice: coalesced uint4 copies (10480 x 16 B).
    {
        const char* gb = (const char*)g_tab;
        for (int idx = threadIdx.x; idx < NTAP * D_VOCAB * 8; idx += THREADS) {
            int r = idx >> 3, c = idx & 7;
            s_tab16[idx] = *(const uint4*)(gb + (size_t)r * 256 + g * 128 + c * 16);
        }
    }
    __syncthreads();

    const float4 bias0 = *(const float4*)(conv_b + g * 64 + l7 * 8);
    const float4 bias1 = *(const float4*)(conv_b + g * 64 + l7 * 8 + 4);
    const int step = 4 * (THREADS / 32);             // 96

    for (int n0 = base + 4 * warp; n0 < end; n0 += step) {
        const int nsel = n0 + q;
        const int row = (nsel < end) ? (nsel - base) : 0;

        // Load this lane's sequence ids from smem (broadcast within quarter).
        int a[CW];
        {
            const int4* sp = (const int4*)(s_ids + row * CW);
            int4 w0 = sp[0], w1 = sp[1], w2 = sp[2], w3 = sp[3];
            a[0] = w0.x * 8 + l7;  a[1] = w0.y * 8 + l7;
            a[2] = w0.z * 8 + l7;  a[3] = w0.w * 8 + l7;
            a[4] = w1.x * 8 + l7;  a[5] = w1.y * 8 + l7;
            a[6] = w1.z * 8 + l7;  a[7] = w1.w * 8 + l7;
            a[8] = w2.x * 8 + l7;  a[9] = w2.y * 8 + l7;
            a[10] = w2.z * 8 + l7; a[11] = w2.w * 8 + l7;
            a[12] = w3.x * 8 + l7; a[13] = w3.y * 8 + l7;
            a[14] = w3.z * 8 + l7; a[15] = w3.w * 8 + l7;
        }

        // Even/odd-t max chains on 8 channels (4 half2) per lane.
        uint4 me, mo;
        #pragma unroll
        for (int t = 0; t < CW; ++t) {
            const int klo = (t < 2) ? (2 - t) : 0;
            const int khi = (t > CW - 3) ? (CW + 1 - t) : NTAP - 1;  // inclusive

            uint4 s[NTAP];
            #pragma unroll
            for (int k = 0; k < NTAP; ++k) {
                if (k < klo || k > khi) continue;
                s[k] = s_tab16[k * TAPSTRIDE16 + a[t + k - 2]];
            }

            uint4 y;
            const int nv = khi - klo + 1;
            if (nv == 5) {
                y = h2add4(h2add4(h2add4(s[0], s[1]), h2add4(s[2], s[3])), s[4]);
            } else if (nv == 4) {
                y = h2add4(h2add4(s[klo], s[klo + 1]), h2add4(s[klo + 2], s[klo + 3]));
            } else {  // nv == 3
                y = h2add4(h2add4(s[klo], s[klo + 1]), s[klo + 2]);
            }

            if (t == 0)      me = y;
            else if (t == 1) mo = y;
            else if ((t & 1) == 0) me = h2max4(me, y);
            else                   mo = h2max4(mo, y);
        }
        const uint4 m = h2max4(me, mo);

        if (nsel < end) {
            float2 c0 = __half22float2(*(const __half2*)&m.x);
            float2 c1 = __half22float2(*(const __half2*)&m.y);
            float2 c2 = __half22float2(*(const __half2*)&m.z);
            float2 c3 = __half22float2(*(const __half2*)&m.w);
            float4 o0, o1;
            o0.x = c0.x + bias0.x; o0.y = c0.y + bias0.y;
            o0.z = c1.x + bias0.z; o0.w = c1.y + bias0.w;
            o1.x = c2.x + bias1.x; o1.y = c2.y + bias1.y;
            o1.z = c3.x + bias1.z; o1.w = c3.y + bias1.w;
            float* op = out + (size_t)nsel * D_EMB + g * 64 + l7 * 8;
            *(float4*)op = o0;
            *(float4*)(op + 4) = o1;
        }
    }
}

// ---------------------------------------------------------------------------
extern "C" void kernel_launch(void* const* d_in, const int* in_sizes, int n_in,
                              void* d_out, int out_size) {
    const int* input = nullptr;
    const float* emb = nullptr;
    const float* conv_w = nullptr;
    const float* conv_b = nullptr;
    for (int i = 0; i < n_in; ++i) {
        switch (in_sizes[i]) {
            case 524288: input  = (const int*)d_in[i];   break;  // ids [128,256,16]
            case 33536:  emb    = (const float*)d_in[i]; break;  // [262,128]
            case 81920:  conv_w = (const float*)d_in[i]; break;  // [128,128,5]
            case 128:    conv_b = (const float*)d_in[i]; break;  // [128]
            default: break;  // lengths (32768) unused
        }
    }

    cudaFuncSetAttribute(precompute_fused,
                         cudaFuncAttributeMaxDynamicSharedMemorySize, PRE_SMEM);
    precompute_fused<<<dim3(66, 4), PRE_THREADS, PRE_SMEM>>>(conv_w, emb);

    cudaFuncSetAttribute(conv_char_kernel,
                         cudaFuncAttributeMaxDynamicSharedMemorySize, SMEM_BYTES);
    conv_char_kernel<<<dim3(NCHUNK, 2), THREADS, SMEM_BYTES>>>(
        input, conv_b, (float*)d_out);
}